// round 13
// baseline (speedup 1.0000x reference)
#include <cuda_runtime.h>
#include <cuda.h>
#include <cuda_fp16.h>
#include <math.h>
#include <float.h>
#include <stdint.h>

#define BB 4
#define SS 2048
#define DD 1024

// ---------------------------------------------------------------------------
// Scratch (static device globals; runtime allocation is forbidden)
// ---------------------------------------------------------------------------
__device__ __half g_qh[BB * SS * DD];
__device__ __half g_kh[BB * SS * DD];
__device__ __half g_vth[BB * DD * SS];          // v transposed [b][d][s]
__device__ float  g_sc[(size_t)BB * SS * SS];   // raw scores
__device__ __half g_ph[(size_t)BB * SS * SS];   // softmax probs (fp16)

// ---------------------------------------------------------------------------
// PTX helpers (baseline ISA only — compute_103 safe)
// ---------------------------------------------------------------------------
__device__ __forceinline__ uint32_t smem_u32(const void* p) {
    uint32_t a;
    asm("{ .reg .u64 t; cvta.to.shared.u64 t, %1; cvt.u32.u64 %0, t; }"
        : "=r"(a) : "l"(p));
    return a;
}
__device__ __forceinline__ void ldsm_x4(uint32_t& r0, uint32_t& r1,
                                        uint32_t& r2, uint32_t& r3, uint32_t addr) {
    asm volatile("ldmatrix.sync.aligned.m8n8.x4.shared.b16 {%0,%1,%2,%3}, [%4];"
                 : "=r"(r0), "=r"(r1), "=r"(r2), "=r"(r3) : "r"(addr));
}
__device__ __forceinline__ void mma16816(float* c, const uint32_t* a, const uint32_t* b) {
    asm volatile(
        "mma.sync.aligned.m16n8k16.row.col.f32.f16.f16.f32 "
        "{%0,%1,%2,%3}, {%4,%5,%6,%7}, {%8,%9}, {%0,%1,%2,%3};"
        : "+f"(c[0]), "+f"(c[1]), "+f"(c[2]), "+f"(c[3])
        : "r"(a[0]), "r"(a[1]), "r"(a[2]), "r"(a[3]), "r"(b[0]), "r"(b[1]));
}
__device__ __forceinline__ void tma_load_3d(uint32_t smem_addr,
                                            const CUtensorMap* map,
                                            int cx, int cy, int cz,
                                            uint32_t mbar) {
    asm volatile(
        "cp.async.bulk.tensor.3d.shared::cta.global.tile.mbarrier::complete_tx::bytes "
        "[%0], [%1, {%2, %3, %4}], [%5];"
        :: "r"(smem_addr), "l"(map), "r"(cx), "r"(cy), "r"(cz), "r"(mbar)
        : "memory");
}
#define MBARRIER_INIT(mbar_addr, count) \
    asm volatile("mbarrier.init.shared.b64 [%0], %1;" \
        :: "r"((uint32_t)(mbar_addr)), "r"((uint32_t)(count)) : "memory")
#define MBARRIER_EXPECT_TX(mbar_addr, tx_bytes) \
    asm volatile("mbarrier.arrive.expect_tx.shared.b64 _, [%0], %1;" \
        :: "r"((uint32_t)(mbar_addr)), "r"((uint32_t)(tx_bytes)) : "memory")
#define MBARRIER_WAIT_PARITY(mbar_smem_addr, phase_parity) do { \
    uint32_t _mbar = (uint32_t)(mbar_smem_addr); \
    uint32_t _parity = (uint32_t)(phase_parity); \
    uint32_t _done; \
    asm volatile( \
        "{\n\t.reg .pred p;\n\t" \
        "mbarrier.try_wait.parity.acquire.cta.shared::cta.b64 p, [%1], %2;\n\t" \
        "selp.b32 %0, 1, 0, p;\n\t}" \
        : "=r"(_done) : "r"(_mbar), "r"(_parity) : "memory"); \
    if (!_done) { \
        asm volatile( \
            "{\n\t.reg .pred P1;\n\t" \
            "WAIT_LOOP_%=:\n\t" \
            "mbarrier.try_wait.parity.acquire.cta.shared::cta.b64 P1, [%0], %1, 0x989680;\n\t" \
            "@P1 bra.uni WAIT_DONE_%=;\n\t" \
            "bra.uni WAIT_LOOP_%=;\n\t" \
            "WAIT_DONE_%=:\n\t}" \
            :: "r"(_mbar), "r"(_parity) : "memory"); \
    } \
} while(0)

__device__ __forceinline__ uint32_t swz128(uint32_t b) {
    return b ^ ((b >> 3) & 0x70);
}

// ---------------------------------------------------------------------------
// Kernel 1 (fused): Givens-rotate Q into q, k (row-major [S,D]) and
// v TRANSPOSED ([b][d][s]), reading Q exactly once.  All batches.
// ---------------------------------------------------------------------------
__global__ __launch_bounds__(256) void prep_kernel(const float* __restrict__ Q,
                                                   const float* __restrict__ rot_w) {
    __shared__ __half th[64][33];
    int d0 = blockIdx.x * 64, s0 = blockIdx.y * 32, b = blockIdx.z;
    int tx = threadIdx.x, ty = threadIdx.y;
    int p = d0 / 2 + tx;
    float cq = rot_w[2 * p],          sq = rot_w[2 * p + 1];
    float ck = rot_w[DD + 2 * p],     sk = rot_w[DD + 2 * p + 1];
    float cv = rot_w[2 * DD + 2 * p], sv = rot_w[2 * DD + 2 * p + 1];
    {
        float i1 = rsqrtf(cq * cq + sq * sq); cq *= i1; sq *= i1;
        float i2 = rsqrtf(ck * ck + sk * sk); ck *= i2; sk *= i2;
        float i3 = rsqrtf(cv * cv + sv * sv); cv *= i3; sv *= i3;
    }
#pragma unroll
    for (int r = 0; r < 4; r++) {
        int srow = s0 + ty + 8 * r;
        size_t off = ((size_t)b * SS + srow) * DD + d0 + 2 * tx;
        float2 x = *(const float2*)(Q + off);
        float y0 = cq * x.x - sq * x.y;
        float y1 = cq * x.y + sq * x.x;
        *(__half2*)(g_qh + off) = __halves2half2(__float2half(y0), __float2half(y1));
        y0 = ck * x.x - sk * x.y;
        y1 = ck * x.y + sk * x.x;
        *(__half2*)(g_kh + off) = __halves2half2(__float2half(y0), __float2half(y1));
        y0 = cv * x.x - sv * x.y;
        y1 = cv * x.y + sv * x.x;
        th[2 * tx][ty + 8 * r] = __float2half(y0);
        th[2 * tx + 1][ty + 8 * r] = __float2half(y1);
    }
    __syncthreads();
#pragma unroll
    for (int r = 0; r < 8; r++) {
        int d = r * 8 + ty;
        size_t o = ((size_t)b * DD + d0 + d) * SS + s0 + tx;
        g_vth[o] = th[d][tx];
    }
}

// ---------------------------------------------------------------------------
// Persistent TMA-fed fp16 NT GEMM:  C[b][M,N] = A[b][M,K] * B[b][N,K]^T
// CTA tile 128x128, 256 threads (8 warps, 2m x 4n of 64x32 warp tiles),
// K-chunk 64 halves (128B SW128 box), 3-stage TMA ring running continuously
// across the CTA's strided tile list (prologue paid once per CTA).
// ---------------------------------------------------------------------------
#define CHUNK 64
#define STAGES 3
#define A_BYTES 16384
#define B_BYTES 16384
#define STAGE_BYTES (A_BYTES + B_BYTES)
#define GSMEM (STAGES * STAGE_BYTES)

__global__ __launch_bounds__(256, 2) void gemm_persistent_kernel(
    const __grid_constant__ CUtensorMap mA,
    const __grid_constant__ CUtensorMap mB,
    float* __restrict__ C, int K, int ldc, size_t strideC,
    int tilesN, int tilesPerBatch, int totalTiles) {
    extern __shared__ __align__(1024) uint8_t sm[];
    __shared__ __align__(8) uint64_t mbar[STAGES];
    uint32_t sbase = smem_u32(sm);
    uint32_t mbase = smem_u32(mbar);

    int tid = threadIdx.x;
    int wid = tid >> 5, lid = tid & 31;
    int wm = wid & 1;      // 0..1 -> 64 rows each
    int wn = wid >> 1;     // 0..3 -> 32 cols each
    int t0 = blockIdx.x, G = gridDim.x;
    int niter = K / CHUNK;
    int myTiles = (totalTiles - t0 + G - 1) / G;
    if (myTiles <= 0) return;
    int gTotal = myTiles * niter;

    // local tile index i -> (batch, m0, n0)
    auto coords = [&](int i, int& b, int& m0, int& n0) {
        int tile = t0 + i * G;
        b = tile / tilesPerBatch;
        int r = tile % tilesPerBatch;
        m0 = (r / tilesN) * 128;
        n0 = (r % tilesN) * 128;
    };
    // issue TMA for global chunk g into stage g%3
    auto issue = [&](int g) {
        int i = g / niter;
        int kc = (g % niter) * CHUNK;
        int b, m0, n0;
        coords(i, b, m0, n0);
        int s = g % 3;
        uint32_t mb = mbase + s * 8;
        uint32_t sd = sbase + s * STAGE_BYTES;
        MBARRIER_EXPECT_TX(mb, STAGE_BYTES);
        tma_load_3d(sd, &mA, kc, m0, b, mb);
        tma_load_3d(sd + A_BYTES, &mB, kc, n0, b, mb);
    };

    if (tid == 0) {
#pragma unroll
        for (int s = 0; s < STAGES; s++) MBARRIER_INIT(mbase + s * 8, 1);
    }
    __syncthreads();

    if (tid == 0) {
        issue(0);
        if (1 < gTotal) issue(1);
    }

    uint32_t rowA[4], rowB[2];
#pragma unroll
    for (int am = 0; am < 4; am++)
        rowA[am] = wm * 64 + am * 16 + (lid & 15);
#pragma unroll
    for (int bq = 0; bq < 2; bq++)
        rowB[bq] = wn * 32 + bq * 16 + (lid & 7) + ((lid >> 4) << 3);
    uint32_t kbA = (lid >> 4) * 16;
    uint32_t kbB = ((lid >> 3) & 1) * 16;

    float acc[4][4][4];
#pragma unroll
    for (int i = 0; i < 4; i++)
#pragma unroll
        for (int j = 0; j < 4; j++)
#pragma unroll
            for (int q = 0; q < 4; q++) acc[i][j][q] = 0.0f;

    int cb, cm0, cn0;                 // current tile coords (for epilogue)
    coords(0, cb, cm0, cn0);

    for (int g = 0; g < gTotal; g++) {
        if (tid == 0 && g + 2 < gTotal) issue(g + 2);
        int s = g % 3;
        MBARRIER_WAIT_PARITY(mbase + s * 8, (g / 3) & 1);
        uint32_t sA = sbase + s * STAGE_BYTES;
        uint32_t sB = sA + A_BYTES;

#pragma unroll
        for (int ks = 0; ks < 4; ks++) {
            uint32_t koff = ks * 32;
            uint32_t a[4][4], bh[4][2];
#pragma unroll
            for (int am = 0; am < 4; am++)
                ldsm_x4(a[am][0], a[am][1], a[am][2], a[am][3],
                        sA + swz128(rowA[am] * 128 + kbA + koff));
#pragma unroll
            for (int bq = 0; bq < 2; bq++) {
                uint32_t r0, r1, r2, r3;
                ldsm_x4(r0, r1, r2, r3, sB + swz128(rowB[bq] * 128 + kbB + koff));
                bh[bq * 2][0] = r0; bh[bq * 2][1] = r1;
                bh[bq * 2 + 1][0] = r2; bh[bq * 2 + 1][1] = r3;
            }
#pragma unroll
            for (int am = 0; am < 4; am++)
#pragma unroll
                for (int bn = 0; bn < 4; bn++)
                    mma16816(acc[am][bn], a[am], bh[bn]);
        }
        __syncthreads();

        if ((g + 1) % niter == 0) {
            // tile finished: write epilogue, reset accumulator, advance coords
#pragma unroll
            for (int am = 0; am < 4; am++) {
                int row = cm0 + wm * 64 + am * 16 + (lid >> 2);
#pragma unroll
                for (int bn = 0; bn < 4; bn++) {
                    int col = cn0 + wn * 32 + bn * 8 + (lid & 3) * 2;
                    float* p0 = C + cb * strideC + (size_t)row * ldc + col;
                    float* p1 = C + cb * strideC + (size_t)(row + 8) * ldc + col;
                    *(float2*)p0 = make_float2(acc[am][bn][0], acc[am][bn][1]);
                    *(float2*)p1 = make_float2(acc[am][bn][2], acc[am][bn][3]);
                }
            }
#pragma unroll
            for (int i = 0; i < 4; i++)
#pragma unroll
                for (int j = 0; j < 4; j++)
#pragma unroll
                    for (int q = 0; q < 4; q++) acc[i][j][q] = 0.0f;
            if (g + 1 < gTotal) coords((g + 1) / niter, cb, cm0, cn0);
        }
    }
}

// ---------------------------------------------------------------------------
// Softmax((2+2x)/scale + bias) == softmax(2x/scale) (shift-invariant).
// ---------------------------------------------------------------------------
__global__ __launch_bounds__(256) void softmax_kernel(const float* __restrict__ scale) {
    size_t rowoff = (size_t)blockIdx.x * SS;
    const float* row = g_sc + rowoff;
    float alpha = 2.0f / scale[0];
    int tid = threadIdx.x;

    float vals[8];
    float lmax = -FLT_MAX;
#pragma unroll
    for (int i = 0; i < 8; i++) {
        float t = row[tid + i * 256] * alpha;
        vals[i] = t;
        lmax = fmaxf(lmax, t);
    }
    __shared__ float sred[8];
    __shared__ float sbc;
    float v = lmax;
#pragma unroll
    for (int o = 16; o > 0; o >>= 1) v = fmaxf(v, __shfl_xor_sync(0xffffffffu, v, o));
    if ((tid & 31) == 0) sred[tid >> 5] = v;
    __syncthreads();
    if (tid == 0) {
        float m = sred[0];
#pragma unroll
        for (int i = 1; i < 8; i++) m = fmaxf(m, sred[i]);
        sbc = m;
    }
    __syncthreads();
    float m = sbc;
    float lsum = 0.0f;
#pragma unroll
    for (int i = 0; i < 8; i++) {
        vals[i] = __expf(vals[i] - m);
        lsum += vals[i];
    }
    v = lsum;
#pragma unroll
    for (int o = 16; o > 0; o >>= 1) v += __shfl_xor_sync(0xffffffffu, v, o);
    __syncthreads();
    if ((tid & 31) == 0) sred[tid >> 5] = v;
    __syncthreads();
    if (tid == 0) {
        float t = 0.0f;
#pragma unroll
        for (int i = 0; i < 8; i++) t += sred[i];
        sbc = 1.0f / t;
    }
    __syncthreads();
    float inv = sbc;
#pragma unroll
    for (int i = 0; i < 8; i++)
        g_ph[rowoff + tid + i * 256] = __float2half(vals[i] * inv);
}

// ---------------------------------------------------------------------------
// Row L2 normalization of out rows (D=1024)
// ---------------------------------------------------------------------------
__global__ __launch_bounds__(256) void normalize_kernel(float* __restrict__ out) {
    float* row = out + (size_t)blockIdx.x * DD;
    int tid = threadIdx.x;
    float v[4];
    float ss = 0.0f;
#pragma unroll
    for (int i = 0; i < 4; i++) {
        v[i] = row[tid + i * 256];
        ss = fmaf(v[i], v[i], ss);
    }
    __shared__ float sred[8];
    __shared__ float sbc;
    float r = ss;
#pragma unroll
    for (int o = 16; o > 0; o >>= 1) r += __shfl_xor_sync(0xffffffffu, r, o);
    if ((tid & 31) == 0) sred[tid >> 5] = r;
    __syncthreads();
    if (tid == 0) {
        float t = 0.0f;
#pragma unroll
        for (int i = 0; i < 8; i++) t += sred[i];
        sbc = rsqrtf(fmaxf(fabsf(t), 1e-8f));
    }
    __syncthreads();
    float inv = sbc;
#pragma unroll
    for (int i = 0; i < 4; i++) row[tid + i * 256] = v[i] * inv;
}

// ---------------------------------------------------------------------------
// Host: tensormap encoding via runtime-resolved driver entry point
// ---------------------------------------------------------------------------
typedef CUresult (*EncodeFn)(
    CUtensorMap*, CUtensorMapDataType, cuuint32_t, void*,
    const cuuint64_t*, const cuuint64_t*, const cuuint32_t*, const cuuint32_t*,
    CUtensorMapInterleave, CUtensorMapSwizzle, CUtensorMapL2promotion,
    CUtensorMapFloatOOBfill);

static void encode_map(EncodeFn enc, CUtensorMap* m, void* ptr,
                       uint64_t d0, uint64_t d1, uint64_t d2,
                       uint32_t box0, uint32_t box1) {
    cuuint64_t dims[3] = {d0, d1, d2};
    cuuint64_t strides[2] = {d0 * 2, d0 * d1 * 2};
    cuuint32_t box[3] = {box0, box1, 1};
    cuuint32_t es[3] = {1, 1, 1};
    enc(m, CU_TENSOR_MAP_DATA_TYPE_FLOAT16, 3, ptr, dims, strides, box, es,
        CU_TENSOR_MAP_INTERLEAVE_NONE, CU_TENSOR_MAP_SWIZZLE_128B,
        CU_TENSOR_MAP_L2_PROMOTION_L2_128B, CU_TENSOR_MAP_FLOAT_OOB_FILL_NONE);
}

extern "C" void kernel_launch(void* const* d_in, const int* in_sizes, int n_in,
                              void* d_out, int out_size) {
    (void)in_sizes; (void)n_in; (void)out_size;
    const float* Q     = (const float*)d_in[0];
    const float* rot_w = (const float*)d_in[1];
    const float* scale = (const float*)d_in[2];
    float* out = (float*)d_out;

    void* fp = nullptr;
    cudaDriverEntryPointQueryResult qr;
    cudaGetDriverEntryPoint("cuTensorMapEncodeTiled", &fp, cudaEnableDefault, &qr);
    EncodeFn enc = (EncodeFn)fp;

    void *p_qh, *p_kh, *p_vth, *p_sc, *p_ph;
    cudaGetSymbolAddress(&p_qh, g_qh);
    cudaGetSymbolAddress(&p_kh, g_kh);
    cudaGetSymbolAddress(&p_vth, g_vth);
    cudaGetSymbolAddress(&p_sc, g_sc);
    cudaGetSymbolAddress(&p_ph, g_ph);

    CUtensorMap mQKa, mQKb, mPVa, mPVb;
    encode_map(enc, &mQKa, p_qh, DD, SS, BB, CHUNK, 128);   // A: q [S,D]
    encode_map(enc, &mQKb, p_kh, DD, SS, BB, CHUNK, 128);   // B: k [S,D]
    encode_map(enc, &mPVa, p_ph, SS, SS, BB, CHUNK, 128);   // A: p [S,S]
    encode_map(enc, &mPVb, p_vth, SS, DD, BB, CHUNK, 128);  // B: v^T [D,S]

    cudaFuncSetAttribute(gemm_persistent_kernel,
                         cudaFuncAttributeMaxDynamicSharedMemorySize, GSMEM);

    int sms = 148;
    cudaDeviceGetAttribute(&sms, cudaDevAttrMultiProcessorCount, 0);
    int gridMax = 2 * sms;

    prep_kernel<<<dim3(DD / 64, SS / 32, BB), dim3(32, 8)>>>(Q, rot_w);

    // scores = q.k^T : 1024 tiles (16x16 per batch x 4)
    {
        int tilesN = SS / 128, tilesPerBatch = (SS / 128) * (SS / 128);
        int total = tilesPerBatch * BB;
        int grid = gridMax < total ? gridMax : total;
        gemm_persistent_kernel<<<grid, 256, GSMEM>>>(
            mQKa, mQKb, (float*)p_sc, DD, SS, (size_t)SS * SS,
            tilesN, tilesPerBatch, total);
    }

    softmax_kernel<<<BB * SS, 256>>>(scale);

    // out = p.v : 512 tiles (16x8 per batch x 4)
    {
        int tilesN = DD / 128, tilesPerBatch = (SS / 128) * (DD / 128);
        int total = tilesPerBatch * BB;
        int grid = gridMax < total ? gridMax : total;
        gemm_persistent_kernel<<<grid, 256, GSMEM>>>(
            mPVa, mPVb, out, SS, DD, (size_t)SS * DD,
            tilesN, tilesPerBatch, total);
    }

    normalize_kernel<<<BB * SS, 256>>>(out);
}

// round 15
// speedup vs baseline: 1.0577x; 1.0577x over previous
#include <cuda_runtime.h>
#include <cuda.h>
#include <cuda_fp16.h>
#include <math.h>
#include <float.h>
#include <stdint.h>

#define BB 4
#define SS 2048
#define DD 1024

// ---------------------------------------------------------------------------
// Scratch (static device globals; runtime allocation is forbidden)
// ---------------------------------------------------------------------------
__device__ __half g_qh[BB * SS * DD];
__device__ __half g_kh[BB * SS * DD];
__device__ __half g_vth[BB * DD * SS];          // v transposed [b][d][s]
__device__ float  g_sc[(size_t)BB * SS * SS];   // raw scores
__device__ __half g_ph[(size_t)BB * SS * SS];   // softmax probs (fp16)

// ---------------------------------------------------------------------------
// PTX helpers (baseline ISA only — compute_103 safe)
// ---------------------------------------------------------------------------
__device__ __forceinline__ uint32_t smem_u32(const void* p) {
    uint32_t a;
    asm("{ .reg .u64 t; cvta.to.shared.u64 t, %1; cvt.u32.u64 %0, t; }"
        : "=r"(a) : "l"(p));
    return a;
}
__device__ __forceinline__ void ldsm_x4(uint32_t& r0, uint32_t& r1,
                                        uint32_t& r2, uint32_t& r3, uint32_t addr) {
    asm volatile("ldmatrix.sync.aligned.m8n8.x4.shared.b16 {%0,%1,%2,%3}, [%4];"
                 : "=r"(r0), "=r"(r1), "=r"(r2), "=r"(r3) : "r"(addr));
}
__device__ __forceinline__ void mma16816(float* c, const uint32_t* a, const uint32_t* b) {
    asm volatile(
        "mma.sync.aligned.m16n8k16.row.col.f32.f16.f16.f32 "
        "{%0,%1,%2,%3}, {%4,%5,%6,%7}, {%8,%9}, {%0,%1,%2,%3};"
        : "+f"(c[0]), "+f"(c[1]), "+f"(c[2]), "+f"(c[3])
        : "r"(a[0]), "r"(a[1]), "r"(a[2]), "r"(a[3]), "r"(b[0]), "r"(b[1]));
}
__device__ __forceinline__ void tma_load_3d(uint32_t smem_addr,
                                            const CUtensorMap* map,
                                            int cx, int cy, int cz,
                                            uint32_t mbar) {
    asm volatile(
        "cp.async.bulk.tensor.3d.shared::cta.global.tile.mbarrier::complete_tx::bytes "
        "[%0], [%1, {%2, %3, %4}], [%5];"
        :: "r"(smem_addr), "l"(map), "r"(cx), "r"(cy), "r"(cz), "r"(mbar)
        : "memory");
}
// Cross-proxy fence: orders this thread's prior generic-proxy smem reads
// before subsequent async-proxy (TMA) writes.  REQUIRED before empty-arrive.
#define FENCE_PROXY_ASYNC() \
    asm volatile("fence.proxy.async.shared::cta;" ::: "memory")
#define MBARRIER_INIT(mbar_addr, count) \
    asm volatile("mbarrier.init.shared.b64 [%0], %1;" \
        :: "r"((uint32_t)(mbar_addr)), "r"((uint32_t)(count)) : "memory")
#define MBARRIER_EXPECT_TX(mbar_addr, tx_bytes) \
    asm volatile("mbarrier.arrive.expect_tx.shared.b64 _, [%0], %1;" \
        :: "r"((uint32_t)(mbar_addr)), "r"((uint32_t)(tx_bytes)) : "memory")
#define MBARRIER_ARRIVE(mbar_addr) \
    asm volatile("mbarrier.arrive.release.cta.shared::cta.b64 _, [%0];" \
        :: "r"((uint32_t)(mbar_addr)) : "memory")
#define MBARRIER_WAIT_PARITY(mbar_smem_addr, phase_parity) do { \
    uint32_t _mbar = (uint32_t)(mbar_smem_addr); \
    uint32_t _parity = (uint32_t)(phase_parity); \
    uint32_t _done; \
    asm volatile( \
        "{\n\t.reg .pred p;\n\t" \
        "mbarrier.try_wait.parity.acquire.cta.shared::cta.b64 p, [%1], %2;\n\t" \
        "selp.b32 %0, 1, 0, p;\n\t}" \
        : "=r"(_done) : "r"(_mbar), "r"(_parity) : "memory"); \
    if (!_done) { \
        asm volatile( \
            "{\n\t.reg .pred P1;\n\t" \
            "WAIT_LOOP_%=:\n\t" \
            "mbarrier.try_wait.parity.acquire.cta.shared::cta.b64 P1, [%0], %1, 0x989680;\n\t" \
            "@P1 bra.uni WAIT_DONE_%=;\n\t" \
            "bra.uni WAIT_LOOP_%=;\n\t" \
            "WAIT_DONE_%=:\n\t}" \
            :: "r"(_mbar), "r"(_parity) : "memory"); \
    } \
} while(0)

__device__ __forceinline__ uint32_t swz128(uint32_t b) {
    return b ^ ((b >> 3) & 0x70);
}

// ---------------------------------------------------------------------------
// Kernel 1 (fused): Givens-rotate Q into q, k (row-major [S,D]) and
// v TRANSPOSED ([b][d][s]), reading Q exactly once.
// ---------------------------------------------------------------------------
__global__ __launch_bounds__(256) void prep_kernel(const float* __restrict__ Q,
                                                   const float* __restrict__ rot_w) {
    __shared__ __half th[64][33];
    int d0 = blockIdx.x * 64, s0 = blockIdx.y * 32, b = blockIdx.z;
    int tx = threadIdx.x, ty = threadIdx.y;
    int p = d0 / 2 + tx;
    float cq = rot_w[2 * p],          sq = rot_w[2 * p + 1];
    float ck = rot_w[DD + 2 * p],     sk = rot_w[DD + 2 * p + 1];
    float cv = rot_w[2 * DD + 2 * p], sv = rot_w[2 * DD + 2 * p + 1];
    {
        float i1 = rsqrtf(cq * cq + sq * sq); cq *= i1; sq *= i1;
        float i2 = rsqrtf(ck * ck + sk * sk); ck *= i2; sk *= i2;
        float i3 = rsqrtf(cv * cv + sv * sv); cv *= i3; sv *= i3;
    }
#pragma unroll
    for (int r = 0; r < 4; r++) {
        int srow = s0 + ty + 8 * r;
        size_t off = ((size_t)b * SS + srow) * DD + d0 + 2 * tx;
        float2 x = *(const float2*)(Q + off);
        float y0 = cq * x.x - sq * x.y;
        float y1 = cq * x.y + sq * x.x;
        *(__half2*)(g_qh + off) = __halves2half2(__float2half(y0), __float2half(y1));
        y0 = ck * x.x - sk * x.y;
        y1 = ck * x.y + sk * x.x;
        *(__half2*)(g_kh + off) = __halves2half2(__float2half(y0), __float2half(y1));
        y0 = cv * x.x - sv * x.y;
        y1 = cv * x.y + sv * x.x;
        th[2 * tx][ty + 8 * r] = __float2half(y0);
        th[2 * tx + 1][ty + 8 * r] = __float2half(y1);
    }
    __syncthreads();
#pragma unroll
    for (int r = 0; r < 8; r++) {
        int d = r * 8 + ty;
        size_t o = ((size_t)b * DD + d0 + d) * SS + s0 + tx;
        g_vth[o] = th[d][tx];
    }
}

// ---------------------------------------------------------------------------
// TMA-fed fp16 NT GEMM:  C[M,N] = A[M,K] * B[N,K]^T
// CTA tile 128x128, 256 threads (8 warps, 2m x 4n of 64x32 warp tiles),
// K-chunk 64 halves, 3-stage TMA pipeline with producer/consumer mbarriers.
// No __syncthreads in the main loop; each consumer thread executes
// fence.proxy.async before its empty-arrive (generic-read -> async-write
// anti-dependency), producer acquires empty before refilling via TMA.
// mbar layout: full[0..2] @ +0..+16, empty[0..2] @ +24..+40.
// ---------------------------------------------------------------------------
#define CHUNK 64
#define STAGES 3
#define A_BYTES 16384
#define B_BYTES 16384
#define STAGE_BYTES (A_BYTES + B_BYTES)
#define GSMEM (STAGES * STAGE_BYTES)

__global__ __launch_bounds__(256, 2) void gemm_tma_kernel(
    const __grid_constant__ CUtensorMap mA,
    const __grid_constant__ CUtensorMap mB,
    float* __restrict__ C, int K, int ldc, size_t strideC) {
    extern __shared__ __align__(1024) uint8_t sm[];
    __shared__ __align__(8) uint64_t mbar[2 * STAGES];
    uint32_t sbase = smem_u32(sm);
    uint32_t mbase = smem_u32(mbar);

    int tid = threadIdx.x;
    int wid = tid >> 5, lid = tid & 31;
    int wm = wid & 1;      // 0..1 -> 64 rows each
    int wn = wid >> 1;     // 0..3 -> 32 cols each
    int b = blockIdx.z;
    int m0 = blockIdx.y * 128, n0 = blockIdx.x * 128;
    int niter = K / CHUNK;

    if (tid == 0) {
#pragma unroll
        for (int s = 0; s < STAGES; s++) {
            MBARRIER_INIT(mbase + s * 8, 1);            // full: TMA tx
            MBARRIER_INIT(mbase + 24 + s * 8, 256);     // empty: all threads
        }
    }
    __syncthreads();

    // prologue: 2 stages ahead (never consumed yet -> no empty wait)
    if (tid == 0) {
#pragma unroll
        for (int p = 0; p < 2; p++) {
            uint32_t mb = mbase + p * 8;
            uint32_t sd = sbase + p * STAGE_BYTES;
            MBARRIER_EXPECT_TX(mb, STAGE_BYTES);
            tma_load_3d(sd, &mA, p * CHUNK, m0, b, mb);
            tma_load_3d(sd + A_BYTES, &mB, p * CHUNK, n0, b, mb);
        }
    }

    uint32_t rowA[4], rowB[2];
#pragma unroll
    for (int am = 0; am < 4; am++)
        rowA[am] = wm * 64 + am * 16 + (lid & 15);
#pragma unroll
    for (int bq = 0; bq < 2; bq++)
        rowB[bq] = wn * 32 + bq * 16 + (lid & 7) + ((lid >> 4) << 3);
    uint32_t kbA = (lid >> 4) * 16;
    uint32_t kbB = ((lid >> 3) & 1) * 16;

    float acc[4][4][4];
#pragma unroll
    for (int i = 0; i < 4; i++)
#pragma unroll
        for (int j = 0; j < 4; j++)
#pragma unroll
            for (int q = 0; q < 4; q++) acc[i][j][q] = 0.0f;

    for (int it = 0; it < niter; it++) {
        // producer: refill stage (it+2)%3 once all consumers released it
        if (tid == 0 && it + 2 < niter) {
            int s2 = (it + 2) % 3;
            if (it >= 1)
                MBARRIER_WAIT_PARITY(mbase + 24 + s2 * 8, ((it - 1) / 3) & 1);
            uint32_t mb = mbase + s2 * 8;
            uint32_t sd = sbase + s2 * STAGE_BYTES;
            MBARRIER_EXPECT_TX(mb, STAGE_BYTES);
            tma_load_3d(sd, &mA, (it + 2) * CHUNK, m0, b, mb);
            tma_load_3d(sd + A_BYTES, &mB, (it + 2) * CHUNK, n0, b, mb);
        }
        int s = it % 3;
        MBARRIER_WAIT_PARITY(mbase + s * 8, (it / 3) & 1);
        uint32_t sA = sbase + s * STAGE_BYTES;
        uint32_t sB = sA + A_BYTES;

#pragma unroll
        for (int ks = 0; ks < 4; ks++) {
            uint32_t koff = ks * 32;
            uint32_t a[4][4], bh[4][2];
#pragma unroll
            for (int am = 0; am < 4; am++)
                ldsm_x4(a[am][0], a[am][1], a[am][2], a[am][3],
                        sA + swz128(rowA[am] * 128 + kbA + koff));
#pragma unroll
            for (int bq = 0; bq < 2; bq++) {
                uint32_t r0, r1, r2, r3;
                ldsm_x4(r0, r1, r2, r3, sB + swz128(rowB[bq] * 128 + kbB + koff));
                bh[bq * 2][0] = r0; bh[bq * 2][1] = r1;
                bh[bq * 2 + 1][0] = r2; bh[bq * 2 + 1][1] = r3;
            }
#pragma unroll
            for (int am = 0; am < 4; am++)
#pragma unroll
                for (int bn = 0; bn < 4; bn++)
                    mma16816(acc[am][bn], a[am], bh[bn]);
        }
        // consumer release: order smem reads before the future TMA overwrite,
        // then arrive on the empty barrier.
        FENCE_PROXY_ASYNC();
        MBARRIER_ARRIVE(mbase + 24 + s * 8);
    }

    // epilogue (registers only; no cross-thread smem dependence)
#pragma unroll
    for (int am = 0; am < 4; am++) {
        int row = m0 + wm * 64 + am * 16 + (lid >> 2);
#pragma unroll
        for (int bn = 0; bn < 4; bn++) {
            int col = n0 + wn * 32 + bn * 8 + (lid & 3) * 2;
            float* p0 = C + b * strideC + (size_t)row * ldc + col;
            float* p1 = C + b * strideC + (size_t)(row + 8) * ldc + col;
            *(float2*)p0 = make_float2(acc[am][bn][0], acc[am][bn][1]);
            *(float2*)p1 = make_float2(acc[am][bn][2], acc[am][bn][3]);
        }
    }
}

// ---------------------------------------------------------------------------
// Softmax((2+2x)/scale + bias) == softmax(2x/scale) (shift-invariant).
// ---------------------------------------------------------------------------
__global__ __launch_bounds__(256) void softmax_kernel(const float* __restrict__ scale) {
    size_t rowoff = (size_t)blockIdx.x * SS;
    const float* row = g_sc + rowoff;
    float alpha = 2.0f / scale[0];
    int tid = threadIdx.x;

    float vals[8];
    float lmax = -FLT_MAX;
#pragma unroll
    for (int i = 0; i < 8; i++) {
        float t = row[tid + i * 256] * alpha;
        vals[i] = t;
        lmax = fmaxf(lmax, t);
    }
    __shared__ float sred[8];
    __shared__ float sbc;
    float v = lmax;
#pragma unroll
    for (int o = 16; o > 0; o >>= 1) v = fmaxf(v, __shfl_xor_sync(0xffffffffu, v, o));
    if ((tid & 31) == 0) sred[tid >> 5] = v;
    __syncthreads();
    if (tid == 0) {
        float m = sred[0];
#pragma unroll
        for (int i = 1; i < 8; i++) m = fmaxf(m, sred[i]);
        sbc = m;
    }
    __syncthreads();
    float m = sbc;
    float lsum = 0.0f;
#pragma unroll
    for (int i = 0; i < 8; i++) {
        vals[i] = __expf(vals[i] - m);
        lsum += vals[i];
    }
    v = lsum;
#pragma unroll
    for (int o = 16; o > 0; o >>= 1) v += __shfl_xor_sync(0xffffffffu, v, o);
    __syncthreads();
    if ((tid & 31) == 0) sred[tid >> 5] = v;
    __syncthreads();
    if (tid == 0) {
        float t = 0.0f;
#pragma unroll
        for (int i = 0; i < 8; i++) t += sred[i];
        sbc = 1.0f / t;
    }
    __syncthreads();
    float inv = sbc;
#pragma unroll
    for (int i = 0; i < 8; i++)
        g_ph[rowoff + tid + i * 256] = __float2half(vals[i] * inv);
}

// ---------------------------------------------------------------------------
// Row L2 normalization of out rows (D=1024)
// ---------------------------------------------------------------------------
__global__ __launch_bounds__(256) void normalize_kernel(float* __restrict__ out) {
    float* row = out + (size_t)blockIdx.x * DD;
    int tid = threadIdx.x;
    float v[4];
    float ss = 0.0f;
#pragma unroll
    for (int i = 0; i < 4; i++) {
        v[i] = row[tid + i * 256];
        ss = fmaf(v[i], v[i], ss);
    }
    __shared__ float sred[8];
    __shared__ float sbc;
    float r = ss;
#pragma unroll
    for (int o = 16; o > 0; o >>= 1) r += __shfl_xor_sync(0xffffffffu, r, o);
    if ((tid & 31) == 0) sred[tid >> 5] = r;
    __syncthreads();
    if (tid == 0) {
        float t = 0.0f;
#pragma unroll
        for (int i = 0; i < 8; i++) t += sred[i];
        sbc = rsqrtf(fmaxf(fabsf(t), 1e-8f));
    }
    __syncthreads();
    float inv = sbc;
#pragma unroll
    for (int i = 0; i < 4; i++) row[tid + i * 256] = v[i] * inv;
}

// ---------------------------------------------------------------------------
// Host: tensormap encoding via runtime-resolved driver entry point
// ---------------------------------------------------------------------------
typedef CUresult (*EncodeFn)(
    CUtensorMap*, CUtensorMapDataType, cuuint32_t, void*,
    const cuuint64_t*, const cuuint64_t*, const cuuint32_t*, const cuuint32_t*,
    CUtensorMapInterleave, CUtensorMapSwizzle, CUtensorMapL2promotion,
    CUtensorMapFloatOOBfill);

static void encode_map(EncodeFn enc, CUtensorMap* m, void* ptr,
                       uint64_t d0, uint64_t d1, uint64_t d2,
                       uint32_t box0, uint32_t box1) {
    cuuint64_t dims[3] = {d0, d1, d2};
    cuuint64_t strides[2] = {d0 * 2, d0 * d1 * 2};
    cuuint32_t box[3] = {box0, box1, 1};
    cuuint32_t es[3] = {1, 1, 1};
    enc(m, CU_TENSOR_MAP_DATA_TYPE_FLOAT16, 3, ptr, dims, strides, box, es,
        CU_TENSOR_MAP_INTERLEAVE_NONE, CU_TENSOR_MAP_SWIZZLE_128B,
        CU_TENSOR_MAP_L2_PROMOTION_L2_128B, CU_TENSOR_MAP_FLOAT_OOB_FILL_NONE);
}

extern "C" void kernel_launch(void* const* d_in, const int* in_sizes, int n_in,
                              void* d_out, int out_size) {
    (void)in_sizes; (void)n_in; (void)out_size;
    const float* Q     = (const float*)d_in[0];
    const float* rot_w = (const float*)d_in[1];
    const float* scale = (const float*)d_in[2];
    float* out = (float*)d_out;

    void* fp = nullptr;
    cudaDriverEntryPointQueryResult qr;
    cudaGetDriverEntryPoint("cuTensorMapEncodeTiled", &fp, cudaEnableDefault, &qr);
    EncodeFn enc = (EncodeFn)fp;

    void *p_qh, *p_kh, *p_vth, *p_sc, *p_ph;
    cudaGetSymbolAddress(&p_qh, g_qh);
    cudaGetSymbolAddress(&p_kh, g_kh);
    cudaGetSymbolAddress(&p_vth, g_vth);
    cudaGetSymbolAddress(&p_sc, g_sc);
    cudaGetSymbolAddress(&p_ph, g_ph);

    CUtensorMap mQKa, mQKb, mPVa, mPVb;
    encode_map(enc, &mQKa, p_qh, DD, SS, BB, CHUNK, 128);   // A: q [S,D]
    encode_map(enc, &mQKb, p_kh, DD, SS, BB, CHUNK, 128);   // B: k [S,D]
    encode_map(enc, &mPVa, p_ph, SS, SS, BB, CHUNK, 128);   // A: p [S,S]
    encode_map(enc, &mPVb, p_vth, SS, DD, BB, CHUNK, 128);  // B: v^T [D,S]

    cudaFuncSetAttribute(gemm_tma_kernel,
                         cudaFuncAttributeMaxDynamicSharedMemorySize, GSMEM);

    prep_kernel<<<dim3(DD / 64, SS / 32, BB), dim3(32, 8)>>>(Q, rot_w);

    gemm_tma_kernel<<<dim3(SS / 128, SS / 128, BB), 256, GSMEM>>>(
        mQKa, mQKb, (float*)p_sc, DD, SS, (size_t)SS * SS);

    softmax_kernel<<<BB * SS, 256>>>(scale);

    gemm_tma_kernel<<<dim3(DD / 128, SS / 128, BB), 256, GSMEM>>>(
        mPVa, mPVb, out, SS, DD, (size_t)SS * DD);

    normalize_kernel<<<BB * SS, 256>>>(out);
}

// round 16
// speedup vs baseline: 1.0732x; 1.0147x over previous
#include <cuda_runtime.h>
#include <cuda.h>
#include <cuda_fp16.h>
#include <math.h>
#include <float.h>
#include <stdint.h>

#define BB 4
#define SS 2048
#define DD 1024

// ---------------------------------------------------------------------------
// Scratch (static device globals; runtime allocation is forbidden)
// ---------------------------------------------------------------------------
__device__ __half g_qh[BB * SS * DD];
__device__ __half g_kh[BB * SS * DD];
__device__ __half g_vth[BB * DD * SS];          // v transposed [b][d][s]
__device__ float  g_sc[(size_t)BB * SS * SS];   // raw scores
__device__ __half g_ph[(size_t)BB * SS * SS];   // softmax probs (fp16)

// ---------------------------------------------------------------------------
// PTX helpers (baseline ISA only — compute_103 safe)
// ---------------------------------------------------------------------------
__device__ __forceinline__ uint32_t smem_u32(const void* p) {
    uint32_t a;
    asm("{ .reg .u64 t; cvta.to.shared.u64 t, %1; cvt.u32.u64 %0, t; }"
        : "=r"(a) : "l"(p));
    return a;
}
__device__ __forceinline__ void ldsm_x4(uint32_t& r0, uint32_t& r1,
                                        uint32_t& r2, uint32_t& r3, uint32_t addr) {
    asm volatile("ldmatrix.sync.aligned.m8n8.x4.shared.b16 {%0,%1,%2,%3}, [%4];"
                 : "=r"(r0), "=r"(r1), "=r"(r2), "=r"(r3) : "r"(addr));
}
__device__ __forceinline__ void mma16816(float* c, const uint32_t* a, const uint32_t* b) {
    asm volatile(
        "mma.sync.aligned.m16n8k16.row.col.f32.f16.f16.f32 "
        "{%0,%1,%2,%3}, {%4,%5,%6,%7}, {%8,%9}, {%0,%1,%2,%3};"
        : "+f"(c[0]), "+f"(c[1]), "+f"(c[2]), "+f"(c[3])
        : "r"(a[0]), "r"(a[1]), "r"(a[2]), "r"(a[3]), "r"(b[0]), "r"(b[1]));
}
__device__ __forceinline__ void tma_load_3d(uint32_t smem_addr,
                                            const CUtensorMap* map,
                                            int cx, int cy, int cz,
                                            uint32_t mbar) {
    asm volatile(
        "cp.async.bulk.tensor.3d.shared::cta.global.tile.mbarrier::complete_tx::bytes "
        "[%0], [%1, {%2, %3, %4}], [%5];"
        :: "r"(smem_addr), "l"(map), "r"(cx), "r"(cy), "r"(cz), "r"(mbar)
        : "memory");
}
#define MBARRIER_INIT(mbar_addr, count) \
    asm volatile("mbarrier.init.shared.b64 [%0], %1;" \
        :: "r"((uint32_t)(mbar_addr)), "r"((uint32_t)(count)) : "memory")
#define MBARRIER_EXPECT_TX(mbar_addr, tx_bytes) \
    asm volatile("mbarrier.arrive.expect_tx.shared.b64 _, [%0], %1;" \
        :: "r"((uint32_t)(mbar_addr)), "r"((uint32_t)(tx_bytes)) : "memory")
#define MBARRIER_WAIT_PARITY(mbar_smem_addr, phase_parity) do { \
    uint32_t _mbar = (uint32_t)(mbar_smem_addr); \
    uint32_t _parity = (uint32_t)(phase_parity); \
    uint32_t _done; \
    asm volatile( \
        "{\n\t.reg .pred p;\n\t" \
        "mbarrier.try_wait.parity.acquire.cta.shared::cta.b64 p, [%1], %2;\n\t" \
        "selp.b32 %0, 1, 0, p;\n\t}" \
        : "=r"(_done) : "r"(_mbar), "r"(_parity) : "memory"); \
    if (!_done) { \
        asm volatile( \
            "{\n\t.reg .pred P1;\n\t" \
            "WAIT_LOOP_%=:\n\t" \
            "mbarrier.try_wait.parity.acquire.cta.shared::cta.b64 P1, [%0], %1, 0x989680;\n\t" \
            "@P1 bra.uni WAIT_DONE_%=;\n\t" \
            "bra.uni WAIT_LOOP_%=;\n\t" \
            "WAIT_DONE_%=:\n\t}" \
            :: "r"(_mbar), "r"(_parity) : "memory"); \
    } \
} while(0)

__device__ __forceinline__ uint32_t swz128(uint32_t b) {
    return b ^ ((b >> 3) & 0x70);
}

// ---------------------------------------------------------------------------
// Kernel 1 (fused): Givens-rotate Q into q, k (row-major [S,D]) and
// v TRANSPOSED ([b][d][s]), reading Q exactly once.
// ---------------------------------------------------------------------------
__global__ __launch_bounds__(256) void prep_kernel(const float* __restrict__ Q,
                                                   const float* __restrict__ rot_w) {
    __shared__ __half th[64][33];
    int d0 = blockIdx.x * 64, s0 = blockIdx.y * 32, b = blockIdx.z;
    int tx = threadIdx.x, ty = threadIdx.y;
    int p = d0 / 2 + tx;
    float cq = rot_w[2 * p],          sq = rot_w[2 * p + 1];
    float ck = rot_w[DD + 2 * p],     sk = rot_w[DD + 2 * p + 1];
    float cv = rot_w[2 * DD + 2 * p], sv = rot_w[2 * DD + 2 * p + 1];
    {
        float i1 = rsqrtf(cq * cq + sq * sq); cq *= i1; sq *= i1;
        float i2 = rsqrtf(ck * ck + sk * sk); ck *= i2; sk *= i2;
        float i3 = rsqrtf(cv * cv + sv * sv); cv *= i3; sv *= i3;
    }
#pragma unroll
    for (int r = 0; r < 4; r++) {
        int srow = s0 + ty + 8 * r;
        size_t off = ((size_t)b * SS + srow) * DD + d0 + 2 * tx;
        float2 x = *(const float2*)(Q + off);
        float y0 = cq * x.x - sq * x.y;
        float y1 = cq * x.y + sq * x.x;
        *(__half2*)(g_qh + off) = __halves2half2(__float2half(y0), __float2half(y1));
        y0 = ck * x.x - sk * x.y;
        y1 = ck * x.y + sk * x.x;
        *(__half2*)(g_kh + off) = __halves2half2(__float2half(y0), __float2half(y1));
        y0 = cv * x.x - sv * x.y;
        y1 = cv * x.y + sv * x.x;
        th[2 * tx][ty + 8 * r] = __float2half(y0);
        th[2 * tx + 1][ty + 8 * r] = __float2half(y1);
    }
    __syncthreads();
#pragma unroll
    for (int r = 0; r < 8; r++) {
        int d = r * 8 + ty;
        size_t o = ((size_t)b * DD + d0 + d) * SS + s0 + tx;
        g_vth[o] = th[d][tx];
    }
}

// ---------------------------------------------------------------------------
// TMA-fed fp16 NT GEMM:  C[M,N] = A[M,K] * B[N,K]^T   (proven R11 shape)
// CTA tile 128x128, 256 threads (8 warps, 2m x 4n of 64x32 warp tiles),
// K-chunk 64 halves (128B SW128 box), 3-stage TMA pipeline, 2 CTAs/SM.
// ---------------------------------------------------------------------------
#define CHUNK 64
#define STAGES 3
#define A_BYTES 16384
#define B_BYTES 16384
#define STAGE_BYTES (A_BYTES + B_BYTES)
#define GSMEM (STAGES * STAGE_BYTES)

__global__ __launch_bounds__(256, 2) void gemm_tma_kernel(
    const __grid_constant__ CUtensorMap mA,
    const __grid_constant__ CUtensorMap mB,
    float* __restrict__ C, int K, int ldc, size_t strideC) {
    extern __shared__ __align__(1024) uint8_t sm[];
    __shared__ __align__(8) uint64_t mbar[STAGES];
    uint32_t sbase = smem_u32(sm);
    uint32_t mbase = smem_u32(mbar);

    int tid = threadIdx.x;
    int wid = tid >> 5, lid = tid & 31;
    int wm = wid & 1;
    int wn = wid >> 1;
    int b = blockIdx.z;
    int m0 = blockIdx.y * 128, n0 = blockIdx.x * 128;
    int niter = K / CHUNK;

    if (tid == 0) {
#pragma unroll
        for (int s = 0; s < STAGES; s++) MBARRIER_INIT(mbase + s * 8, 1);
    }
    __syncthreads();

    if (tid == 0) {
#pragma unroll
        for (int p = 0; p < 2; p++) {
            uint32_t mb = mbase + p * 8;
            uint32_t sd = sbase + p * STAGE_BYTES;
            MBARRIER_EXPECT_TX(mb, STAGE_BYTES);
            tma_load_3d(sd, &mA, p * CHUNK, m0, b, mb);
            tma_load_3d(sd + A_BYTES, &mB, p * CHUNK, n0, b, mb);
        }
    }

    uint32_t rowA[4], rowB[2];
#pragma unroll
    for (int am = 0; am < 4; am++)
        rowA[am] = wm * 64 + am * 16 + (lid & 15);
#pragma unroll
    for (int bq = 0; bq < 2; bq++)
        rowB[bq] = wn * 32 + bq * 16 + (lid & 7) + ((lid >> 4) << 3);
    uint32_t kbA = (lid >> 4) * 16;
    uint32_t kbB = ((lid >> 3) & 1) * 16;

    float acc[4][4][4];
#pragma unroll
    for (int i = 0; i < 4; i++)
#pragma unroll
        for (int j = 0; j < 4; j++)
#pragma unroll
            for (int q = 0; q < 4; q++) acc[i][j][q] = 0.0f;

    for (int it = 0; it < niter; it++) {
        if (tid == 0 && it + 2 < niter) {
            int s2 = (it + 2) % 3;
            uint32_t mb = mbase + s2 * 8;
            uint32_t sd = sbase + s2 * STAGE_BYTES;
            MBARRIER_EXPECT_TX(mb, STAGE_BYTES);
            tma_load_3d(sd, &mA, (it + 2) * CHUNK, m0, b, mb);
            tma_load_3d(sd + A_BYTES, &mB, (it + 2) * CHUNK, n0, b, mb);
        }
        int s = it % 3;
        MBARRIER_WAIT_PARITY(mbase + s * 8, (it / 3) & 1);
        uint32_t sA = sbase + s * STAGE_BYTES;
        uint32_t sB = sA + A_BYTES;

#pragma unroll
        for (int ks = 0; ks < 4; ks++) {
            uint32_t koff = ks * 32;
            uint32_t a[4][4], bh[4][2];
#pragma unroll
            for (int am = 0; am < 4; am++)
                ldsm_x4(a[am][0], a[am][1], a[am][2], a[am][3],
                        sA + swz128(rowA[am] * 128 + kbA + koff));
#pragma unroll
            for (int bq = 0; bq < 2; bq++) {
                uint32_t r0, r1, r2, r3;
                ldsm_x4(r0, r1, r2, r3, sB + swz128(rowB[bq] * 128 + kbB + koff));
                bh[bq * 2][0] = r0; bh[bq * 2][1] = r1;
                bh[bq * 2 + 1][0] = r2; bh[bq * 2 + 1][1] = r3;
            }
#pragma unroll
            for (int am = 0; am < 4; am++)
#pragma unroll
                for (int bn = 0; bn < 4; bn++)
                    mma16816(acc[am][bn], a[am], bh[bn]);
        }
        __syncthreads();
    }

    // epilogue
#pragma unroll
    for (int am = 0; am < 4; am++) {
        int row = m0 + wm * 64 + am * 16 + (lid >> 2);
#pragma unroll
        for (int bn = 0; bn < 4; bn++) {
            int col = n0 + wn * 32 + bn * 8 + (lid & 3) * 2;
            float* p0 = C + b * strideC + (size_t)row * ldc + col;
            float* p1 = C + b * strideC + (size_t)(row + 8) * ldc + col;
            *(float2*)p0 = make_float2(acc[am][bn][0], acc[am][bn][1]);
            *(float2*)p1 = make_float2(acc[am][bn][2], acc[am][bn][3]);
        }
    }
}

// ---------------------------------------------------------------------------
// Softmax((2+2x)/scale + bias) == softmax(2x/scale) (shift-invariant).
// Vectorized: 2x float4 loads, 4x half2 stores per thread.
// ---------------------------------------------------------------------------
__global__ __launch_bounds__(256) void softmax_kernel(const float* __restrict__ scale) {
    size_t rowoff = (size_t)blockIdx.x * SS;
    const float4* row4 = (const float4*)(g_sc + rowoff);
    float alpha = 2.0f / scale[0];
    int tid = threadIdx.x;

    float4 v0 = row4[tid];
    float4 v1 = row4[tid + 256];
    float vals[8] = {v0.x * alpha, v0.y * alpha, v0.z * alpha, v0.w * alpha,
                     v1.x * alpha, v1.y * alpha, v1.z * alpha, v1.w * alpha};
    float lmax = vals[0];
#pragma unroll
    for (int i = 1; i < 8; i++) lmax = fmaxf(lmax, vals[i]);

    __shared__ float sred[8];
    __shared__ float sbc;
    float v = lmax;
#pragma unroll
    for (int o = 16; o > 0; o >>= 1) v = fmaxf(v, __shfl_xor_sync(0xffffffffu, v, o));
    if ((tid & 31) == 0) sred[tid >> 5] = v;
    __syncthreads();
    if (tid == 0) {
        float m = sred[0];
#pragma unroll
        for (int i = 1; i < 8; i++) m = fmaxf(m, sred[i]);
        sbc = m;
    }
    __syncthreads();
    float m = sbc;
    float lsum = 0.0f;
#pragma unroll
    for (int i = 0; i < 8; i++) {
        vals[i] = __expf(vals[i] - m);
        lsum += vals[i];
    }
    v = lsum;
#pragma unroll
    for (int o = 16; o > 0; o >>= 1) v += __shfl_xor_sync(0xffffffffu, v, o);
    __syncthreads();
    if ((tid & 31) == 0) sred[tid >> 5] = v;
    __syncthreads();
    if (tid == 0) {
        float t = 0.0f;
#pragma unroll
        for (int i = 0; i < 8; i++) t += sred[i];
        sbc = 1.0f / t;
    }
    __syncthreads();
    float inv = sbc;

    __half2* out2 = (__half2*)(g_ph + rowoff);
#pragma unroll
    for (int j = 0; j < 2; j++) {
        __half2 h0 = __floats2half2_rn(vals[j * 4 + 0] * inv, vals[j * 4 + 1] * inv);
        __half2 h1 = __floats2half2_rn(vals[j * 4 + 2] * inv, vals[j * 4 + 3] * inv);
        int base = (tid + j * 256) * 2;   // half2 index of this float4 group
        out2[base] = h0;
        out2[base + 1] = h1;
    }
}

// ---------------------------------------------------------------------------
// Row L2 normalization: exactly one float4 per thread (1024 = 256*4).
// ---------------------------------------------------------------------------
__global__ __launch_bounds__(256) void normalize_kernel(float* __restrict__ out) {
    float4* row4 = (float4*)(out + (size_t)blockIdx.x * DD);
    int tid = threadIdx.x;
    float4 x = row4[tid];
    float ss = x.x * x.x + x.y * x.y + x.z * x.z + x.w * x.w;

    __shared__ float sred[8];
    __shared__ float sbc;
    float r = ss;
#pragma unroll
    for (int o = 16; o > 0; o >>= 1) r += __shfl_xor_sync(0xffffffffu, r, o);
    if ((tid & 31) == 0) sred[tid >> 5] = r;
    __syncthreads();
    if (tid == 0) {
        float t = 0.0f;
#pragma unroll
        for (int i = 0; i < 8; i++) t += sred[i];
        sbc = rsqrtf(fmaxf(fabsf(t), 1e-8f));
    }
    __syncthreads();
    float inv = sbc;
    x.x *= inv; x.y *= inv; x.z *= inv; x.w *= inv;
    row4[tid] = x;
}

// ---------------------------------------------------------------------------
// Host: tensormap encoding via runtime-resolved driver entry point
// ---------------------------------------------------------------------------
typedef CUresult (*EncodeFn)(
    CUtensorMap*, CUtensorMapDataType, cuuint32_t, void*,
    const cuuint64_t*, const cuuint64_t*, const cuuint32_t*, const cuuint32_t*,
    CUtensorMapInterleave, CUtensorMapSwizzle, CUtensorMapL2promotion,
    CUtensorMapFloatOOBfill);

static void encode_map(EncodeFn enc, CUtensorMap* m, void* ptr,
                       uint64_t d0, uint64_t d1, uint64_t d2,
                       uint32_t box0, uint32_t box1) {
    cuuint64_t dims[3] = {d0, d1, d2};
    cuuint64_t strides[2] = {d0 * 2, d0 * d1 * 2};
    cuuint32_t box[3] = {box0, box1, 1};
    cuuint32_t es[3] = {1, 1, 1};
    enc(m, CU_TENSOR_MAP_DATA_TYPE_FLOAT16, 3, ptr, dims, strides, box, es,
        CU_TENSOR_MAP_INTERLEAVE_NONE, CU_TENSOR_MAP_SWIZZLE_128B,
        CU_TENSOR_MAP_L2_PROMOTION_L2_128B, CU_TENSOR_MAP_FLOAT_OOB_FILL_NONE);
}

extern "C" void kernel_launch(void* const* d_in, const int* in_sizes, int n_in,
                              void* d_out, int out_size) {
    (void)in_sizes; (void)n_in; (void)out_size;
    const float* Q     = (const float*)d_in[0];
    const float* rot_w = (const float*)d_in[1];
    const float* scale = (const float*)d_in[2];
    float* out = (float*)d_out;

    void* fp = nullptr;
    cudaDriverEntryPointQueryResult qr;
    cudaGetDriverEntryPoint("cuTensorMapEncodeTiled", &fp, cudaEnableDefault, &qr);
    EncodeFn enc = (EncodeFn)fp;

    void *p_qh, *p_kh, *p_vth, *p_sc, *p_ph;
    cudaGetSymbolAddress(&p_qh, g_qh);
    cudaGetSymbolAddress(&p_kh, g_kh);
    cudaGetSymbolAddress(&p_vth, g_vth);
    cudaGetSymbolAddress(&p_sc, g_sc);
    cudaGetSymbolAddress(&p_ph, g_ph);

    CUtensorMap mQKa, mQKb, mPVa, mPVb;
    encode_map(enc, &mQKa, p_qh, DD, SS, BB, CHUNK, 128);   // A: q [S,D]
    encode_map(enc, &mQKb, p_kh, DD, SS, BB, CHUNK, 128);   // B: k [S,D]
    encode_map(enc, &mPVa, p_ph, SS, SS, BB, CHUNK, 128);   // A: p [S,S]
    encode_map(enc, &mPVb, p_vth, SS, DD, BB, CHUNK, 128);  // B: v^T [D,S]

    cudaFuncSetAttribute(gemm_tma_kernel,
                         cudaFuncAttributeMaxDynamicSharedMemorySize, GSMEM);

    prep_kernel<<<dim3(DD / 64, SS / 32, BB), dim3(32, 8)>>>(Q, rot_w);

    gemm_tma_kernel<<<dim3(SS / 128, SS / 128, BB), 256, GSMEM>>>(
        mQKa, mQKb, (float*)p_sc, DD, SS, (size_t)SS * SS);

    softmax_kernel<<<BB * SS, 256>>>(scale);

    gemm_tma_kernel<<<dim3(DD / 128, SS / 128, BB), 256, GSMEM>>>(
        mPVa, mPVb, out, SS, DD, (size_t)SS * DD);

    normalize_kernel<<<BB * SS, 256>>>(out);
}